// round 5
// baseline (speedup 1.0000x reference)
#include <cuda_runtime.h>
#include <cuda_bf16.h>
#include <math.h>
#include <stdint.h>

#define B_SZ 1024
#define LATD 64
#define FCON 256
#define IN0  320
#define HIDD 512
#define INTER 576
#define NOUT 512
#define NE   8
#define GH   64
#define K0P  2624   // 8*320+64 (bias tail)
#define K1P  4672   // 8*576+64

__device__ float g_coeff[B_SZ*NE];
__device__ float g_out0[B_SZ*HIDD];
__device__ float g_out1[B_SZ*HIDD];
__device__ __nv_bfloat16 g_Ahi[B_SZ*K1P];
__device__ __nv_bfloat16 g_Alo[B_SZ*K1P];
__device__ __nv_bfloat16 g_W0hi[NOUT*K0P];
__device__ __nv_bfloat16 g_W0lo[NOUT*K0P];
__device__ __nv_bfloat16 g_W1hi[NOUT*K1P];
__device__ __nv_bfloat16 g_W1lo[NOUT*K1P];
__device__ __nv_bfloat16 g_W2hi[NOUT*K1P];
__device__ __nv_bfloat16 g_W2lo[NOUT*K1P];

__device__ __forceinline__ float elu_f(float x){ return x > 0.0f ? x : expm1f(x); }

__device__ __forceinline__ uint32_t smem_u32(const void* p){
    uint32_t a;
    asm("{ .reg .u64 t; cvta.to.shared.u64 t, %1; cvt.u32.u64 %0, t; }" : "=r"(a) : "l"(p));
    return a;
}

#define CP16(s, g) asm volatile("cp.async.cg.shared.global [%0], [%1], 16;" :: "r"(s), "l"(g))
#define CP_COMMIT() asm volatile("cp.async.commit_group;" ::: "memory")
#define CP_WAIT1()  asm volatile("cp.async.wait_group 1;" ::: "memory")
#define CP_WAIT0()  asm volatile("cp.async.wait_group 0;" ::: "memory")

#define LDSM4(r0,r1,r2,r3,addr) \
    asm volatile("ldmatrix.sync.aligned.m8n8.x4.shared.b16 {%0,%1,%2,%3}, [%4];" \
        : "=r"(r0), "=r"(r1), "=r"(r2), "=r"(r3) : "r"(addr))

#define MMA16816(c, a0,a1,a2,a3, b0,b1) \
    asm volatile("mma.sync.aligned.m16n8k16.row.col.f32.bf16.bf16.f32 " \
        "{%0,%1,%2,%3}, {%4,%5,%6,%7}, {%8,%9}, {%0,%1,%2,%3};" \
        : "+f"((c)[0]), "+f"((c)[1]), "+f"((c)[2]), "+f"((c)[3]) \
        : "r"(a0), "r"(a1), "r"(a2), "r"(a3), "r"(b0), "r"(b1))

__device__ __forceinline__ void split_pair(float a, float b, uint32_t& h, uint32_t& l){
    __nv_bfloat16 ha = __float2bfloat16_rn(a), hb = __float2bfloat16_rn(b);
    __nv_bfloat16 la = __float2bfloat16_rn(a - __bfloat162float(ha));
    __nv_bfloat16 lb = __float2bfloat16_rn(b - __bfloat162float(hb));
    __nv_bfloat162 H = __halves2bfloat162(ha, hb), L = __halves2bfloat162(la, lb);
    h = *reinterpret_cast<uint32_t*>(&H); l = *reinterpret_cast<uint32_t*>(&L);
}

// ---------------- gate ----------------
__global__ __launch_bounds__(GH) void gate_kernel(
    const float* __restrict__ z, const float* __restrict__ c,
    const float* __restrict__ gw1, const float* __restrict__ gb1,
    const float* __restrict__ gw2, const float* __restrict__ gb2,
    const float* __restrict__ gw3, const float* __restrict__ gb3)
{
    __shared__ float x[IN0], h1[GH], h2[GH], lg[NE];
    int b = blockIdx.x, t = threadIdx.x;
    x[t] = z[b*LATD + t];
    for (int i = t; i < FCON; i += GH) x[LATD+i] = c[b*FCON + i];
    __syncthreads();
    float acc = gb1[t];
    #pragma unroll 8
    for (int i = 0; i < IN0; i++) acc += x[i]*gw1[i*GH + t];
    h1[t] = elu_f(acc);
    __syncthreads();
    acc = gb2[t];
    #pragma unroll 8
    for (int i = 0; i < GH; i++) acc += h1[i]*gw2[i*GH + t];
    h2[t] = elu_f(acc);
    __syncthreads();
    if (t < NE){
        float a = gb3[t];
        #pragma unroll 8
        for (int i = 0; i < GH; i++) a += h2[i]*gw3[i*NE + t];
        lg[t] = a;
    }
    __syncthreads();
    if (t < NE){
        float m = lg[0];
        #pragma unroll
        for (int i = 1; i < NE; i++) m = fmaxf(m, lg[i]);
        float s = 0.f;
        #pragma unroll
        for (int i = 0; i < NE; i++) s += expf(lg[i]-m);
        g_coeff[b*NE + t] = expf(lg[t]-m)/s;
    }
}

// ---------------- fused transpose + bias-tail for all 3 layers ----------------
// layer z: W fp32 [KTOT,512] -> bf16 hi/lo [512,KP]; cols [KTOT,KP): bias rows then 0.
__global__ void transpose_all(
    const float* __restrict__ w0, const float* __restrict__ b0,
    const float* __restrict__ w1, const float* __restrict__ b1,
    const float* __restrict__ w2, const float* __restrict__ b2)
{
    const float *W, *bias; __nv_bfloat16 *Whi, *Wlo; int KTOT, KP;
    if (blockIdx.z == 0){ W=w0; bias=b0; Whi=g_W0hi; Wlo=g_W0lo; KTOT=NE*IN0;   KP=K0P; }
    else if (blockIdx.z == 1){ W=w1; bias=b1; Whi=g_W1hi; Wlo=g_W1lo; KTOT=NE*INTER; KP=K1P; }
    else { W=w2; bias=b2; Whi=g_W2hi; Wlo=g_W2lo; KTOT=NE*INTER; KP=K1P; }

    int k0 = blockIdx.x*32;
    if (k0 >= KP) return;
    int n0 = blockIdx.y*32;
    int x = threadIdx.x, y = threadIdx.y;   // (32, 8)

    if (k0 < KTOT){
        __shared__ float tile[32][33];
        #pragma unroll
        for (int j = 0; j < 32; j += 8)
            tile[y+j][x] = W[(size_t)(k0+y+j)*NOUT + n0 + x];
        __syncthreads();
        #pragma unroll
        for (int j = 0; j < 32; j += 8){
            float v = tile[x][y+j];
            int n = n0+y+j, k = k0+x;
            __nv_bfloat16 h = __float2bfloat16_rn(v);
            __nv_bfloat16 l = __float2bfloat16_rn(v - __bfloat162float(h));
            Whi[(size_t)n*KP + k] = h; Wlo[(size_t)n*KP + k] = l;
        }
    } else {
        int k = k0 + x, j = k - KTOT;
        #pragma unroll
        for (int r = 0; r < 32; r += 8){
            int n = n0 + y + r;
            float v = (j < NE) ? bias[j*NOUT + n] : 0.0f;
            __nv_bfloat16 h = __float2bfloat16_rn(v);
            __nv_bfloat16 l = __float2bfloat16_rn(v - __bfloat162float(h));
            Whi[(size_t)n*KP + k] = h; Wlo[(size_t)n*KP + k] = l;
        }
    }
}

// ---------------- A' build ----------------
__global__ __launch_bounds__(256) void prep_kernel(
    const float* __restrict__ z, const float* __restrict__ prev,
    int prev_w, int IN, int KP,
    __nv_bfloat16* __restrict__ Ahi, __nv_bfloat16* __restrict__ Alo)
{
    int b = blockIdx.x, tid = threadIdx.x;
    __shared__ float cf[NE];
    if (tid < NE) cf[tid] = g_coeff[b*NE + tid];
    __syncthreads();
    const float4* z4 = (const float4*)(z + (size_t)b*LATD);
    const float4* p4 = (const float4*)(prev + (size_t)b*prev_w);
    uint4* oh = (uint4*)(Ahi + (size_t)b*KP);
    uint4* ol = (uint4*)(Alo + (size_t)b*KP);
    int inu = IN >> 3, main_u = NE*inu, NU = KP >> 3;
    for (int u = tid; u < NU; u += 256){
        float v[8];
        if (u < main_u){
            int e = u/inu, i8 = (u - e*inu) << 3;
            float s = cf[e];
            float4 x0, x1;
            if (i8 < LATD){ x0 = z4[i8>>2]; x1 = z4[(i8>>2)+1]; }
            else { int q = (i8-LATD)>>2; x0 = p4[q]; x1 = p4[q+1]; }
            v[0]=x0.x*s; v[1]=x0.y*s; v[2]=x0.z*s; v[3]=x0.w*s;
            v[4]=x1.x*s; v[5]=x1.y*s; v[6]=x1.z*s; v[7]=x1.w*s;
        } else {
            int j = (u - main_u) << 3;
            #pragma unroll
            for (int l = 0; l < 8; l++) v[l] = (j+l < NE) ? cf[j+l] : 0.0f;
        }
        uint4 hh, ll;
        split_pair(v[0],v[1],hh.x,ll.x); split_pair(v[2],v[3],hh.y,ll.y);
        split_pair(v[4],v[5],hh.z,ll.z); split_pair(v[6],v[7],hh.w,ll.w);
        oh[u] = hh; ol[u] = ll;
    }
}

// ---------------- mma.sync GEMM, 3-stage cp.async, one sync per tile ----------------
// CTA 64x64, BK=64; 8 warps (2m x 4n), warp tile 32x16, 3-pass bf16 split.
// Stage (32KB): AH@0 AL@8192 BH@16384 BL@24576; 3 stages = 96KB.
#define STG_SZ 32768
#define GSMEM (3*STG_SZ)

template<int KT, bool ACT>
__global__ __launch_bounds__(256) void gemm_kernel(
    const __nv_bfloat16* __restrict__ Ahi, const __nv_bfloat16* __restrict__ Alo,
    const __nv_bfloat16* __restrict__ Whi, const __nv_bfloat16* __restrict__ Wlo,
    float* __restrict__ out)
{
    constexpr int KP = KT*64;
    extern __shared__ char smem[];
    const uint32_t sb = smem_u32(smem);
    const int tid = threadIdx.x, wid = tid >> 5, L = tid & 31;
    const int m0 = blockIdx.y*64, n0 = blockIdx.x*64;
    const int wm = (wid & 1)*32, wn = (wid >> 1)*16;

    uint32_t s_o[2];
    const __nv_bfloat16 *gah[2], *gal[2], *gbh[2], *gbl[2];
    #pragma unroll
    for (int r = 0; r < 2; r++){
        int ch = tid + r*256, row = ch >> 3, kc = ch & 7;
        s_o[r] = row*128 + ((kc*16) ^ ((row & 7) << 4));
        gah[r] = Ahi + (size_t)(m0+row)*KP + kc*8;
        gal[r] = Alo + (size_t)(m0+row)*KP + kc*8;
        gbh[r] = Whi + (size_t)(n0+row)*KP + kc*8;
        gbl[r] = Wlo + (size_t)(n0+row)*KP + kc*8;
    }

    const int alf = (L & 7) + ((L >> 3) & 1)*8;
    const int acb = (L >> 4)*16;
    const int axor = (alf & 7) << 4;
    const uint32_t arow0 = (uint32_t)(wm + alf)*128;
    const uint32_t arow1 = (uint32_t)(wm + 16 + alf)*128;
    const int blf = (L & 7) + (L >> 4)*8;
    const int bcb = ((L >> 3) & 1)*16;
    const int bxor = (blf & 7) << 4;
    const uint32_t brow = (uint32_t)(wn + blf)*128;

    float acc[2][2][4];
    #pragma unroll
    for (int i = 0; i < 2; i++)
        #pragma unroll
        for (int j = 0; j < 2; j++)
            #pragma unroll
            for (int q = 0; q < 4; q++) acc[i][j][q] = 0.0f;

    // prologue: tiles 0 and 1
    #pragma unroll
    for (int pt = 0; pt < 2; pt++){
        uint32_t st = sb + pt*STG_SZ;
        size_t kb = (size_t)pt*64;
        #pragma unroll
        for (int r = 0; r < 2; r++){
            CP16(st +         s_o[r], gah[r] + kb);
            CP16(st + 8192  + s_o[r], gal[r] + kb);
            CP16(st + 16384 + s_o[r], gbh[r] + kb);
            CP16(st + 24576 + s_o[r], gbl[r] + kb);
        }
        CP_COMMIT();
    }

    int stg = 0;
    for (int t = 0; t < KT; t++){
        if (t < KT-1) CP_WAIT1(); else CP_WAIT0();
        __syncthreads();

        if (t + 2 < KT){
            int ws = stg + 2; if (ws >= 3) ws -= 3;
            uint32_t st = sb + ws*STG_SZ;
            size_t kb = (size_t)(t+2)*64;
            #pragma unroll
            for (int r = 0; r < 2; r++){
                CP16(st +         s_o[r], gah[r] + kb);
                CP16(st + 8192  + s_o[r], gal[r] + kb);
                CP16(st + 16384 + s_o[r], gbh[r] + kb);
                CP16(st + 24576 + s_o[r], gbl[r] + kb);
            }
            CP_COMMIT();
        }

        const uint32_t st = sb + stg*STG_SZ;
        #pragma unroll
        for (int ks = 0; ks < 4; ks++){
            const uint32_t ca = (uint32_t)((ks*32 + acb) ^ axor);
            const uint32_t cb = (uint32_t)((ks*32 + bcb) ^ bxor);
            uint32_t ah0[4], ah1[4], al0[4], al1[4], bh[4], bl[4];
            LDSM4(ah0[0],ah0[1],ah0[2],ah0[3], st + arow0 + ca);
            LDSM4(ah1[0],ah1[1],ah1[2],ah1[3], st + arow1 + ca);
            LDSM4(al0[0],al0[1],al0[2],al0[3], st + 8192 + arow0 + ca);
            LDSM4(al1[0],al1[1],al1[2],al1[3], st + 8192 + arow1 + ca);
            LDSM4(bh[0],bh[1],bh[2],bh[3],     st + 16384 + brow + cb);
            LDSM4(bl[0],bl[1],bl[2],bl[3],     st + 24576 + brow + cb);

            MMA16816(acc[0][0], ah0[0],ah0[1],ah0[2],ah0[3], bh[0],bh[1]);
            MMA16816(acc[0][1], ah0[0],ah0[1],ah0[2],ah0[3], bh[2],bh[3]);
            MMA16816(acc[1][0], ah1[0],ah1[1],ah1[2],ah1[3], bh[0],bh[1]);
            MMA16816(acc[1][1], ah1[0],ah1[1],ah1[2],ah1[3], bh[2],bh[3]);
            MMA16816(acc[0][0], al0[0],al0[1],al0[2],al0[3], bh[0],bh[1]);
            MMA16816(acc[0][1], al0[0],al0[1],al0[2],al0[3], bh[2],bh[3]);
            MMA16816(acc[1][0], al1[0],al1[1],al1[2],al1[3], bh[0],bh[1]);
            MMA16816(acc[1][1], al1[0],al1[1],al1[2],al1[3], bh[2],bh[3]);
            MMA16816(acc[0][0], ah0[0],ah0[1],ah0[2],ah0[3], bl[0],bl[1]);
            MMA16816(acc[0][1], ah0[0],ah0[1],ah0[2],ah0[3], bl[2],bl[3]);
            MMA16816(acc[1][0], ah1[0],ah1[1],ah1[2],ah1[3], bl[0],bl[1]);
            MMA16816(acc[1][1], ah1[0],ah1[1],ah1[2],ah1[3], bl[2],bl[3]);
        }
        stg = (stg == 2) ? 0 : stg + 1;
    }

    const int g = L >> 2, tg = L & 3;
    #pragma unroll
    for (int i = 0; i < 2; i++){
        #pragma unroll
        for (int j = 0; j < 2; j++){
            int row = m0 + wm + i*16 + g;
            int col = n0 + wn + j*8 + 2*tg;
            float2 v0, v1;
            v0.x = ACT ? elu_f(acc[i][j][0]) : acc[i][j][0];
            v0.y = ACT ? elu_f(acc[i][j][1]) : acc[i][j][1];
            v1.x = ACT ? elu_f(acc[i][j][2]) : acc[i][j][2];
            v1.y = ACT ? elu_f(acc[i][j][3]) : acc[i][j][3];
            *(float2*)(out + (size_t)row*NOUT + col) = v0;
            *(float2*)(out + (size_t)(row+8)*NOUT + col) = v1;
        }
    }
}

extern "C" void kernel_launch(void* const* d_in, const int* in_sizes, int n_in,
                              void* d_out, int out_size)
{
    const float* z   = (const float*)d_in[0];
    const float* c   = (const float*)d_in[1];
    const float* w0  = (const float*)d_in[2];
    const float* b0  = (const float*)d_in[3];
    const float* w1  = (const float*)d_in[4];
    const float* b1  = (const float*)d_in[5];
    const float* w2  = (const float*)d_in[6];
    const float* b2  = (const float*)d_in[7];
    const float* gw1 = (const float*)d_in[8];
    const float* gb1 = (const float*)d_in[9];
    const float* gw2 = (const float*)d_in[10];
    const float* gb2 = (const float*)d_in[11];
    const float* gw3 = (const float*)d_in[12];
    const float* gb3 = (const float*)d_in[13];
    float* out = (float*)d_out;

    float *out0, *out1;
    __nv_bfloat16 *Ahi, *Alo, *W0hi, *W0lo, *W1hi, *W1lo, *W2hi, *W2lo;
    cudaGetSymbolAddress((void**)&out0, g_out0);
    cudaGetSymbolAddress((void**)&out1, g_out1);
    cudaGetSymbolAddress((void**)&Ahi, g_Ahi);
    cudaGetSymbolAddress((void**)&Alo, g_Alo);
    cudaGetSymbolAddress((void**)&W0hi, g_W0hi);
    cudaGetSymbolAddress((void**)&W0lo, g_W0lo);
    cudaGetSymbolAddress((void**)&W1hi, g_W1hi);
    cudaGetSymbolAddress((void**)&W1lo, g_W1lo);
    cudaGetSymbolAddress((void**)&W2hi, g_W2hi);
    cudaGetSymbolAddress((void**)&W2lo, g_W2lo);

    cudaFuncSetAttribute(gemm_kernel<K0P/64, true>,  cudaFuncAttributeMaxDynamicSharedMemorySize, GSMEM);
    cudaFuncSetAttribute(gemm_kernel<K1P/64, true>,  cudaFuncAttributeMaxDynamicSharedMemorySize, GSMEM);
    cudaFuncSetAttribute(gemm_kernel<K1P/64, false>, cudaFuncAttributeMaxDynamicSharedMemorySize, GSMEM);

    dim3 gg(8, 16);   // 128 CTAs

    transpose_all<<<dim3(K1P/32, 16, 3), dim3(32, 8)>>>(w0, b0, w1, b1, w2, b2);
    gate_kernel<<<B_SZ, GH>>>(z, c, gw1, gb1, gw2, gb2, gw3, gb3);

    prep_kernel<<<B_SZ, 256>>>(z, c, FCON, IN0, K0P, Ahi, Alo);
    gemm_kernel<K0P/64, true><<<gg, 256, GSMEM>>>(Ahi, Alo, W0hi, W0lo, out0);

    prep_kernel<<<B_SZ, 256>>>(z, out0, HIDD, INTER, K1P, Ahi, Alo);
    gemm_kernel<K1P/64, true><<<gg, 256, GSMEM>>>(Ahi, Alo, W1hi, W1lo, out1);

    prep_kernel<<<B_SZ, 256>>>(z, out1, HIDD, INTER, K1P, Ahi, Alo);
    gemm_kernel<K1P/64, false><<<gg, 256, GSMEM>>>(Ahi, Alo, W2hi, W2lo, out);
}

// round 6
// speedup vs baseline: 1.0117x; 1.0117x over previous
#include <cuda_runtime.h>
#include <cuda_bf16.h>
#include <math.h>
#include <stdint.h>

#define B_SZ 1024
#define LATD 64
#define FCON 256
#define IN0  320
#define HIDD 512
#define INTER 576
#define NOUT 512
#define NE   8
#define GH   64
#define K0P  2624   // 8*320+64 (bias tail)
#define K1P  4672   // 8*576+64

__device__ float g_coeff[B_SZ*NE];
__device__ float g_out0[B_SZ*HIDD];
__device__ float g_out1[B_SZ*HIDD];
__device__ __nv_bfloat16 g_Ahi[B_SZ*K1P];
__device__ __nv_bfloat16 g_Alo[B_SZ*K1P];
__device__ __nv_bfloat16 g_W0hi[NOUT*K0P];
__device__ __nv_bfloat16 g_W0lo[NOUT*K0P];
__device__ __nv_bfloat16 g_W1hi[NOUT*K1P];
__device__ __nv_bfloat16 g_W1lo[NOUT*K1P];
__device__ __nv_bfloat16 g_W2hi[NOUT*K1P];
__device__ __nv_bfloat16 g_W2lo[NOUT*K1P];

__device__ __forceinline__ float elu_f(float x){ return x > 0.0f ? x : expm1f(x); }

__device__ __forceinline__ uint32_t smem_u32(const void* p){
    uint32_t a;
    asm("{ .reg .u64 t; cvta.to.shared.u64 t, %1; cvt.u32.u64 %0, t; }" : "=r"(a) : "l"(p));
    return a;
}

#define CP16(s, g) asm volatile("cp.async.cg.shared.global [%0], [%1], 16;" :: "r"(s), "l"(g))
#define CP_COMMIT() asm volatile("cp.async.commit_group;" ::: "memory")
#define CP_WAIT1()  asm volatile("cp.async.wait_group 1;" ::: "memory")
#define CP_WAIT0()  asm volatile("cp.async.wait_group 0;" ::: "memory")

#define LDSM4(r0,r1,r2,r3,addr) \
    asm volatile("ldmatrix.sync.aligned.m8n8.x4.shared.b16 {%0,%1,%2,%3}, [%4];" \
        : "=r"(r0), "=r"(r1), "=r"(r2), "=r"(r3) : "r"(addr))

#define MMA16816(c, a0,a1,a2,a3, b0,b1) \
    asm volatile("mma.sync.aligned.m16n8k16.row.col.f32.bf16.bf16.f32 " \
        "{%0,%1,%2,%3}, {%4,%5,%6,%7}, {%8,%9}, {%0,%1,%2,%3};" \
        : "+f"((c)[0]), "+f"((c)[1]), "+f"((c)[2]), "+f"((c)[3]) \
        : "r"(a0), "r"(a1), "r"(a2), "r"(a3), "r"(b0), "r"(b1))

__device__ __forceinline__ void split_pair(float a, float b, uint32_t& h, uint32_t& l){
    __nv_bfloat16 ha = __float2bfloat16_rn(a), hb = __float2bfloat16_rn(b);
    __nv_bfloat16 la = __float2bfloat16_rn(a - __bfloat162float(ha));
    __nv_bfloat16 lb = __float2bfloat16_rn(b - __bfloat162float(hb));
    __nv_bfloat162 H = __halves2bfloat162(ha, hb), L = __halves2bfloat162(la, lb);
    h = *reinterpret_cast<uint32_t*>(&H); l = *reinterpret_cast<uint32_t*>(&L);
}

// ---------------- fused transpose + bias-tail for all 3 layers ----------------
__global__ void transpose_all(
    const float* __restrict__ w0, const float* __restrict__ b0,
    const float* __restrict__ w1, const float* __restrict__ b1,
    const float* __restrict__ w2, const float* __restrict__ b2)
{
    const float *W, *bias; __nv_bfloat16 *Whi, *Wlo; int KTOT, KP;
    if (blockIdx.z == 0){ W=w0; bias=b0; Whi=g_W0hi; Wlo=g_W0lo; KTOT=NE*IN0;   KP=K0P; }
    else if (blockIdx.z == 1){ W=w1; bias=b1; Whi=g_W1hi; Wlo=g_W1lo; KTOT=NE*INTER; KP=K1P; }
    else { W=w2; bias=b2; Whi=g_W2hi; Wlo=g_W2lo; KTOT=NE*INTER; KP=K1P; }

    int k0 = blockIdx.x*32;
    if (k0 >= KP) return;
    int n0 = blockIdx.y*32;
    int x = threadIdx.x, y = threadIdx.y;   // (32, 8)

    if (k0 < KTOT){
        __shared__ float tile[32][33];
        #pragma unroll
        for (int j = 0; j < 32; j += 8)
            tile[y+j][x] = W[(size_t)(k0+y+j)*NOUT + n0 + x];
        __syncthreads();
        #pragma unroll
        for (int j = 0; j < 32; j += 8){
            float v = tile[x][y+j];
            int n = n0+y+j, k = k0+x;
            __nv_bfloat16 h = __float2bfloat16_rn(v);
            __nv_bfloat16 l = __float2bfloat16_rn(v - __bfloat162float(h));
            Whi[(size_t)n*KP + k] = h; Wlo[(size_t)n*KP + k] = l;
        }
    } else {
        int k = k0 + x, j = k - KTOT;
        #pragma unroll
        for (int r = 0; r < 32; r += 8){
            int n = n0 + y + r;
            float v = (j < NE) ? bias[j*NOUT + n] : 0.0f;
            __nv_bfloat16 h = __float2bfloat16_rn(v);
            __nv_bfloat16 l = __float2bfloat16_rn(v - __bfloat162float(h));
            Whi[(size_t)n*KP + k] = h; Wlo[(size_t)n*KP + k] = l;
        }
    }
}

// ---------------- fused gate + layer-0 A' build ----------------
__global__ __launch_bounds__(256) void gate_prep_kernel(
    const float* __restrict__ z, const float* __restrict__ c,
    const float* __restrict__ gw1, const float* __restrict__ gb1,
    const float* __restrict__ gw2, const float* __restrict__ gb2,
    const float* __restrict__ gw3, const float* __restrict__ gb3,
    __nv_bfloat16* __restrict__ Ahi, __nv_bfloat16* __restrict__ Alo)
{
    __shared__ float x[IN0], h1[GH], h2[GH], lg[NE], cf[NE];
    int b = blockIdx.x, tid = threadIdx.x;

    if (tid < LATD) x[tid] = z[b*LATD + tid];
    for (int i = tid; i < FCON; i += 256) x[LATD+i] = c[b*FCON + i];
    __syncthreads();

    if (tid < GH){
        float acc = gb1[tid];
        #pragma unroll 8
        for (int i = 0; i < IN0; i++) acc += x[i]*gw1[i*GH + tid];
        h1[tid] = elu_f(acc);
    }
    __syncthreads();
    if (tid < GH){
        float acc = gb2[tid];
        #pragma unroll 8
        for (int i = 0; i < GH; i++) acc += h1[i]*gw2[i*GH + tid];
        h2[tid] = elu_f(acc);
    }
    __syncthreads();
    if (tid < NE){
        float a = gb3[tid];
        #pragma unroll 8
        for (int i = 0; i < GH; i++) a += h2[i]*gw3[i*NE + tid];
        lg[tid] = a;
    }
    __syncthreads();
    if (tid < NE){
        float m = lg[0];
        #pragma unroll
        for (int i = 1; i < NE; i++) m = fmaxf(m, lg[i]);
        float s = 0.f;
        #pragma unroll
        for (int i = 0; i < NE; i++) s += expf(lg[i]-m);
        float cv = expf(lg[tid]-m)/s;
        cf[tid] = cv;
        g_coeff[b*NE + tid] = cv;
    }
    __syncthreads();

    // layer-0 A' straight from smem x[] = [z, c]
    uint4* oh = (uint4*)(Ahi + (size_t)b*K0P);
    uint4* ol = (uint4*)(Alo + (size_t)b*K0P);
    const int inu = IN0 >> 3, main_u = NE*inu, NU = K0P >> 3;
    for (int u = tid; u < NU; u += 256){
        float v[8];
        if (u < main_u){
            int e = u/inu, i8 = (u - e*inu) << 3;
            float s = cf[e];
            #pragma unroll
            for (int l = 0; l < 8; l++) v[l] = x[i8+l]*s;
        } else {
            int j = (u - main_u) << 3;
            #pragma unroll
            for (int l = 0; l < 8; l++) v[l] = (j+l < NE) ? cf[j+l] : 0.0f;
        }
        uint4 hh, ll;
        split_pair(v[0],v[1],hh.x,ll.x); split_pair(v[2],v[3],hh.y,ll.y);
        split_pair(v[4],v[5],hh.z,ll.z); split_pair(v[6],v[7],hh.w,ll.w);
        oh[u] = hh; ol[u] = ll;
    }
}

// ---------------- A' build for layers 1/2 ----------------
__global__ __launch_bounds__(256) void prep_kernel(
    const float* __restrict__ z, const float* __restrict__ prev,
    int prev_w, int IN, int KP,
    __nv_bfloat16* __restrict__ Ahi, __nv_bfloat16* __restrict__ Alo)
{
    int b = blockIdx.x, tid = threadIdx.x;
    __shared__ float cf[NE];
    if (tid < NE) cf[tid] = g_coeff[b*NE + tid];
    __syncthreads();
    const float4* z4 = (const float4*)(z + (size_t)b*LATD);
    const float4* p4 = (const float4*)(prev + (size_t)b*prev_w);
    uint4* oh = (uint4*)(Ahi + (size_t)b*KP);
    uint4* ol = (uint4*)(Alo + (size_t)b*KP);
    int inu = IN >> 3, main_u = NE*inu, NU = KP >> 3;
    for (int u = tid; u < NU; u += 256){
        float v[8];
        if (u < main_u){
            int e = u/inu, i8 = (u - e*inu) << 3;
            float s = cf[e];
            float4 x0, x1;
            if (i8 < LATD){ x0 = z4[i8>>2]; x1 = z4[(i8>>2)+1]; }
            else { int q = (i8-LATD)>>2; x0 = p4[q]; x1 = p4[q+1]; }
            v[0]=x0.x*s; v[1]=x0.y*s; v[2]=x0.z*s; v[3]=x0.w*s;
            v[4]=x1.x*s; v[5]=x1.y*s; v[6]=x1.z*s; v[7]=x1.w*s;
        } else {
            int j = (u - main_u) << 3;
            #pragma unroll
            for (int l = 0; l < 8; l++) v[l] = (j+l < NE) ? cf[j+l] : 0.0f;
        }
        uint4 hh, ll;
        split_pair(v[0],v[1],hh.x,ll.x); split_pair(v[2],v[3],hh.y,ll.y);
        split_pair(v[4],v[5],hh.z,ll.z); split_pair(v[6],v[7],hh.w,ll.w);
        oh[u] = hh; ol[u] = ll;
    }
}

// ---------------- mma.sync GEMM, 3-stage cp.async + register frag double-buffer ----------------
#define STG_SZ 32768
#define GSMEM (3*STG_SZ)

template<int KT, bool ACT>
__global__ __launch_bounds__(256) void gemm_kernel(
    const __nv_bfloat16* __restrict__ Ahi, const __nv_bfloat16* __restrict__ Alo,
    const __nv_bfloat16* __restrict__ Whi, const __nv_bfloat16* __restrict__ Wlo,
    float* __restrict__ out)
{
    constexpr int KP = KT*64;
    extern __shared__ char smem[];
    const uint32_t sb = smem_u32(smem);
    const int tid = threadIdx.x, wid = tid >> 5, L = tid & 31;
    const int m0 = blockIdx.y*64, n0 = blockIdx.x*64;
    const int wm = (wid & 1)*32, wn = (wid >> 1)*16;

    uint32_t s_o[2];
    const __nv_bfloat16 *gah[2], *gal[2], *gbh[2], *gbl[2];
    #pragma unroll
    for (int r = 0; r < 2; r++){
        int ch = tid + r*256, row = ch >> 3, kc = ch & 7;
        s_o[r] = row*128 + ((kc*16) ^ ((row & 7) << 4));
        gah[r] = Ahi + (size_t)(m0+row)*KP + kc*8;
        gal[r] = Alo + (size_t)(m0+row)*KP + kc*8;
        gbh[r] = Whi + (size_t)(n0+row)*KP + kc*8;
        gbl[r] = Wlo + (size_t)(n0+row)*KP + kc*8;
    }

    const int alf = (L & 7) + ((L >> 3) & 1)*8;
    const int acb = (L >> 4)*16;
    const int axor = (alf & 7) << 4;
    const uint32_t arow0 = (uint32_t)(wm + alf)*128;
    const uint32_t arow1 = (uint32_t)(wm + 16 + alf)*128;
    const int blf = (L & 7) + (L >> 4)*8;
    const int bcb = ((L >> 3) & 1)*16;
    const int bxor = (blf & 7) << 4;
    const uint32_t brow = (uint32_t)(wn + blf)*128;

    float acc[2][2][4];
    #pragma unroll
    for (int i = 0; i < 2; i++)
        #pragma unroll
        for (int j = 0; j < 2; j++)
            #pragma unroll
            for (int q = 0; q < 4; q++) acc[i][j][q] = 0.0f;

    // fragment double buffers: fa = {ah0[4], ah1[4], al0[4], al1[4]}, fb = {bh[4], bl[4]}
    uint32_t fa[2][16], fb[2][8];

#define LOADFR(p, st, ks) do { \
    const uint32_t _ca = (uint32_t)(((ks)*32 + acb) ^ axor); \
    const uint32_t _cb = (uint32_t)(((ks)*32 + bcb) ^ bxor); \
    LDSM4(fa[p][0], fa[p][1], fa[p][2], fa[p][3],   (st) + arow0 + _ca); \
    LDSM4(fa[p][4], fa[p][5], fa[p][6], fa[p][7],   (st) + arow1 + _ca); \
    LDSM4(fa[p][8], fa[p][9], fa[p][10],fa[p][11],  (st) + 8192 + arow0 + _ca); \
    LDSM4(fa[p][12],fa[p][13],fa[p][14],fa[p][15],  (st) + 8192 + arow1 + _ca); \
    LDSM4(fb[p][0], fb[p][1], fb[p][2], fb[p][3],   (st) + 16384 + brow + _cb); \
    LDSM4(fb[p][4], fb[p][5], fb[p][6], fb[p][7],   (st) + 24576 + brow + _cb); \
} while(0)

#define DOMMA(p) do { \
    MMA16816(acc[0][0], fa[p][0], fa[p][1], fa[p][2], fa[p][3],  fb[p][0], fb[p][1]); \
    MMA16816(acc[0][1], fa[p][0], fa[p][1], fa[p][2], fa[p][3],  fb[p][2], fb[p][3]); \
    MMA16816(acc[1][0], fa[p][4], fa[p][5], fa[p][6], fa[p][7],  fb[p][0], fb[p][1]); \
    MMA16816(acc[1][1], fa[p][4], fa[p][5], fa[p][6], fa[p][7],  fb[p][2], fb[p][3]); \
    MMA16816(acc[0][0], fa[p][8], fa[p][9], fa[p][10],fa[p][11], fb[p][0], fb[p][1]); \
    MMA16816(acc[0][1], fa[p][8], fa[p][9], fa[p][10],fa[p][11], fb[p][2], fb[p][3]); \
    MMA16816(acc[1][0], fa[p][12],fa[p][13],fa[p][14],fa[p][15], fb[p][0], fb[p][1]); \
    MMA16816(acc[1][1], fa[p][12],fa[p][13],fa[p][14],fa[p][15], fb[p][2], fb[p][3]); \
    MMA16816(acc[0][0], fa[p][0], fa[p][1], fa[p][2], fa[p][3],  fb[p][4], fb[p][5]); \
    MMA16816(acc[0][1], fa[p][0], fa[p][1], fa[p][2], fa[p][3],  fb[p][6], fb[p][7]); \
    MMA16816(acc[1][0], fa[p][4], fa[p][5], fa[p][6], fa[p][7],  fb[p][4], fb[p][5]); \
    MMA16816(acc[1][1], fa[p][4], fa[p][5], fa[p][6], fa[p][7],  fb[p][6], fb[p][7]); \
} while(0)

    // prologue: stage tiles 0 and 1
    #pragma unroll
    for (int pt = 0; pt < 2; pt++){
        uint32_t st = sb + pt*STG_SZ;
        size_t kb = (size_t)pt*64;
        #pragma unroll
        for (int r = 0; r < 2; r++){
            CP16(st +         s_o[r], gah[r] + kb);
            CP16(st + 8192  + s_o[r], gal[r] + kb);
            CP16(st + 16384 + s_o[r], gbh[r] + kb);
            CP16(st + 24576 + s_o[r], gbl[r] + kb);
        }
        CP_COMMIT();
    }

    int stg = 0;
    for (int t = 0; t < KT; t++){
        if (t < KT-1) CP_WAIT1(); else CP_WAIT0();
        __syncthreads();

        if (t + 2 < KT){
            int ws = stg + 2; if (ws >= 3) ws -= 3;
            uint32_t st = sb + ws*STG_SZ;
            size_t kb = (size_t)(t+2)*64;
            #pragma unroll
            for (int r = 0; r < 2; r++){
                CP16(st +         s_o[r], gah[r] + kb);
                CP16(st + 8192  + s_o[r], gal[r] + kb);
                CP16(st + 16384 + s_o[r], gbh[r] + kb);
                CP16(st + 24576 + s_o[r], gbl[r] + kb);
            }
            CP_COMMIT();
        }

        const uint32_t st = sb + stg*STG_SZ;
        LOADFR(0, st, 0);
        LOADFR(1, st, 1);
        DOMMA(0);
        LOADFR(0, st, 2);
        DOMMA(1);
        LOADFR(1, st, 3);
        DOMMA(0);
        DOMMA(1);
        stg = (stg == 2) ? 0 : stg + 1;
    }

    const int g = L >> 2, tg = L & 3;
    #pragma unroll
    for (int i = 0; i < 2; i++){
        #pragma unroll
        for (int j = 0; j < 2; j++){
            int row = m0 + wm + i*16 + g;
            int col = n0 + wn + j*8 + 2*tg;
            float2 v0, v1;
            v0.x = ACT ? elu_f(acc[i][j][0]) : acc[i][j][0];
            v0.y = ACT ? elu_f(acc[i][j][1]) : acc[i][j][1];
            v1.x = ACT ? elu_f(acc[i][j][2]) : acc[i][j][2];
            v1.y = ACT ? elu_f(acc[i][j][3]) : acc[i][j][3];
            *(float2*)(out + (size_t)row*NOUT + col) = v0;
            *(float2*)(out + (size_t)(row+8)*NOUT + col) = v1;
        }
    }
#undef LOADFR
#undef DOMMA
}

extern "C" void kernel_launch(void* const* d_in, const int* in_sizes, int n_in,
                              void* d_out, int out_size)
{
    const float* z   = (const float*)d_in[0];
    const float* c   = (const float*)d_in[1];
    const float* w0  = (const float*)d_in[2];
    const float* b0  = (const float*)d_in[3];
    const float* w1  = (const float*)d_in[4];
    const float* b1  = (const float*)d_in[5];
    const float* w2  = (const float*)d_in[6];
    const float* b2  = (const float*)d_in[7];
    const float* gw1 = (const float*)d_in[8];
    const float* gb1 = (const float*)d_in[9];
    const float* gw2 = (const float*)d_in[10];
    const float* gb2 = (const float*)d_in[11];
    const float* gw3 = (const float*)d_in[12];
    const float* gb3 = (const float*)d_in[13];
    float* out = (float*)d_out;

    float *out0, *out1;
    __nv_bfloat16 *Ahi, *Alo, *W0hi, *W0lo, *W1hi, *W1lo, *W2hi, *W2lo;
    cudaGetSymbolAddress((void**)&out0, g_out0);
    cudaGetSymbolAddress((void**)&out1, g_out1);
    cudaGetSymbolAddress((void**)&Ahi, g_Ahi);
    cudaGetSymbolAddress((void**)&Alo, g_Alo);
    cudaGetSymbolAddress((void**)&W0hi, g_W0hi);
    cudaGetSymbolAddress((void**)&W0lo, g_W0lo);
    cudaGetSymbolAddress((void**)&W1hi, g_W1hi);
    cudaGetSymbolAddress((void**)&W1lo, g_W1lo);
    cudaGetSymbolAddress((void**)&W2hi, g_W2hi);
    cudaGetSymbolAddress((void**)&W2lo, g_W2lo);

    cudaFuncSetAttribute(gemm_kernel<K0P/64, true>,  cudaFuncAttributeMaxDynamicSharedMemorySize, GSMEM);
    cudaFuncSetAttribute(gemm_kernel<K1P/64, true>,  cudaFuncAttributeMaxDynamicSharedMemorySize, GSMEM);
    cudaFuncSetAttribute(gemm_kernel<K1P/64, false>, cudaFuncAttributeMaxDynamicSharedMemorySize, GSMEM);

    dim3 gg(8, 16);   // 128 CTAs

    transpose_all<<<dim3(K1P/32, 16, 3), dim3(32, 8)>>>(w0, b0, w1, b1, w2, b2);
    gate_prep_kernel<<<B_SZ, 256>>>(z, c, gw1, gb1, gw2, gb2, gw3, gb3, Ahi, Alo);
    gemm_kernel<K0P/64, true><<<gg, 256, GSMEM>>>(Ahi, Alo, W0hi, W0lo, out0);

    prep_kernel<<<B_SZ, 256>>>(z, out0, HIDD, INTER, K1P, Ahi, Alo);
    gemm_kernel<K1P/64, true><<<gg, 256, GSMEM>>>(Ahi, Alo, W1hi, W1lo, out1);

    prep_kernel<<<B_SZ, 256>>>(z, out1, HIDD, INTER, K1P, Ahi, Alo);
    gemm_kernel<K1P/64, false><<<gg, 256, GSMEM>>>(Ahi, Alo, W2hi, W2lo, out);
}

// round 7
// speedup vs baseline: 1.1040x; 1.0912x over previous
#include <cuda_runtime.h>
#include <cuda_bf16.h>
#include <math.h>
#include <stdint.h>

#define B_SZ 1024
#define LATD 64
#define FCON 256
#define IN0  320
#define HIDD 512
#define INTER 576
#define NOUT 512
#define NE   8
#define GH   64
#define K0P  2624   // 8*320+64 (bias tail)
#define K1P  4672   // 8*576+64

__device__ float g_coeff[B_SZ*NE];
__device__ float g_part0[B_SZ*NOUT];
__device__ float g_part1[B_SZ*NOUT];
__device__ __nv_bfloat16 g_Ahi[B_SZ*K1P];
__device__ __nv_bfloat16 g_Alo[B_SZ*K1P];
__device__ __nv_bfloat16 g_W0hi[NOUT*K0P];
__device__ __nv_bfloat16 g_W0lo[NOUT*K0P];
__device__ __nv_bfloat16 g_W1hi[NOUT*K1P];
__device__ __nv_bfloat16 g_W1lo[NOUT*K1P];
__device__ __nv_bfloat16 g_W2hi[NOUT*K1P];
__device__ __nv_bfloat16 g_W2lo[NOUT*K1P];

__device__ __forceinline__ float elu_f(float x){ return x > 0.0f ? x : expm1f(x); }

__device__ __forceinline__ uint32_t smem_u32(const void* p){
    uint32_t a;
    asm("{ .reg .u64 t; cvta.to.shared.u64 t, %1; cvt.u32.u64 %0, t; }" : "=r"(a) : "l"(p));
    return a;
}

#define CP16(s, g) asm volatile("cp.async.cg.shared.global [%0], [%1], 16;" :: "r"(s), "l"(g))
#define CP_COMMIT() asm volatile("cp.async.commit_group;" ::: "memory")
#define CP_WAIT1()  asm volatile("cp.async.wait_group 1;" ::: "memory")
#define CP_WAIT0()  asm volatile("cp.async.wait_group 0;" ::: "memory")

#define LDSM4(r0,r1,r2,r3,addr) \
    asm volatile("ldmatrix.sync.aligned.m8n8.x4.shared.b16 {%0,%1,%2,%3}, [%4];" \
        : "=r"(r0), "=r"(r1), "=r"(r2), "=r"(r3) : "r"(addr))

#define MMA16816(c, a0,a1,a2,a3, b0,b1) \
    asm volatile("mma.sync.aligned.m16n8k16.row.col.f32.bf16.bf16.f32 " \
        "{%0,%1,%2,%3}, {%4,%5,%6,%7}, {%8,%9}, {%0,%1,%2,%3};" \
        : "+f"((c)[0]), "+f"((c)[1]), "+f"((c)[2]), "+f"((c)[3]) \
        : "r"(a0), "r"(a1), "r"(a2), "r"(a3), "r"(b0), "r"(b1))

__device__ __forceinline__ void split_pair(float a, float b, uint32_t& h, uint32_t& l){
    __nv_bfloat16 ha = __float2bfloat16_rn(a), hb = __float2bfloat16_rn(b);
    __nv_bfloat16 la = __float2bfloat16_rn(a - __bfloat162float(ha));
    __nv_bfloat16 lb = __float2bfloat16_rn(b - __bfloat162float(hb));
    __nv_bfloat162 H = __halves2bfloat162(ha, hb), L = __halves2bfloat162(la, lb);
    h = *reinterpret_cast<uint32_t*>(&H); l = *reinterpret_cast<uint32_t*>(&L);
}

// ---------------- fused transpose + bias-tail for all 3 layers ----------------
__global__ void transpose_all(
    const float* __restrict__ w0, const float* __restrict__ b0,
    const float* __restrict__ w1, const float* __restrict__ b1,
    const float* __restrict__ w2, const float* __restrict__ b2)
{
    const float *W, *bias; __nv_bfloat16 *Whi, *Wlo; int KTOT, KP;
    if (blockIdx.z == 0){ W=w0; bias=b0; Whi=g_W0hi; Wlo=g_W0lo; KTOT=NE*IN0;   KP=K0P; }
    else if (blockIdx.z == 1){ W=w1; bias=b1; Whi=g_W1hi; Wlo=g_W1lo; KTOT=NE*INTER; KP=K1P; }
    else { W=w2; bias=b2; Whi=g_W2hi; Wlo=g_W2lo; KTOT=NE*INTER; KP=K1P; }

    int k0 = blockIdx.x*32;
    if (k0 >= KP) return;
    int n0 = blockIdx.y*32;
    int x = threadIdx.x, y = threadIdx.y;   // (32, 8)

    if (k0 < KTOT){
        __shared__ float tile[32][33];
        #pragma unroll
        for (int j = 0; j < 32; j += 8)
            tile[y+j][x] = W[(size_t)(k0+y+j)*NOUT + n0 + x];
        __syncthreads();
        #pragma unroll
        for (int j = 0; j < 32; j += 8){
            float v = tile[x][y+j];
            int n = n0+y+j, k = k0+x;
            __nv_bfloat16 h = __float2bfloat16_rn(v);
            __nv_bfloat16 l = __float2bfloat16_rn(v - __bfloat162float(h));
            Whi[(size_t)n*KP + k] = h; Wlo[(size_t)n*KP + k] = l;
        }
    } else {
        int k = k0 + x, j = k - KTOT;
        #pragma unroll
        for (int r = 0; r < 32; r += 8){
            int n = n0 + y + r;
            float v = (j < NE) ? bias[j*NOUT + n] : 0.0f;
            __nv_bfloat16 h = __float2bfloat16_rn(v);
            __nv_bfloat16 l = __float2bfloat16_rn(v - __bfloat162float(h));
            Whi[(size_t)n*KP + k] = h; Wlo[(size_t)n*KP + k] = l;
        }
    }
}

// ---------------- fused gate + layer-0 A' build ----------------
__global__ __launch_bounds__(256) void gate_prep_kernel(
    const float* __restrict__ z, const float* __restrict__ c,
    const float* __restrict__ gw1, const float* __restrict__ gb1,
    const float* __restrict__ gw2, const float* __restrict__ gb2,
    const float* __restrict__ gw3, const float* __restrict__ gb3,
    __nv_bfloat16* __restrict__ Ahi, __nv_bfloat16* __restrict__ Alo)
{
    __shared__ float x[IN0], h1[GH], h2[GH], lg[NE], cf[NE];
    int b = blockIdx.x, tid = threadIdx.x;

    if (tid < LATD) x[tid] = z[b*LATD + tid];
    for (int i = tid; i < FCON; i += 256) x[LATD+i] = c[b*FCON + i];
    __syncthreads();

    if (tid < GH){
        float acc = gb1[tid];
        #pragma unroll 8
        for (int i = 0; i < IN0; i++) acc += x[i]*gw1[i*GH + tid];
        h1[tid] = elu_f(acc);
    }
    __syncthreads();
    if (tid < GH){
        float acc = gb2[tid];
        #pragma unroll 8
        for (int i = 0; i < GH; i++) acc += h1[i]*gw2[i*GH + tid];
        h2[tid] = elu_f(acc);
    }
    __syncthreads();
    if (tid < NE){
        float a = gb3[tid];
        #pragma unroll 8
        for (int i = 0; i < GH; i++) a += h2[i]*gw3[i*NE + tid];
        lg[tid] = a;
    }
    __syncthreads();
    if (tid < NE){
        float m = lg[0];
        #pragma unroll
        for (int i = 1; i < NE; i++) m = fmaxf(m, lg[i]);
        float s = 0.f;
        #pragma unroll
        for (int i = 0; i < NE; i++) s += expf(lg[i]-m);
        float cv = expf(lg[tid]-m)/s;
        cf[tid] = cv;
        g_coeff[b*NE + tid] = cv;
    }
    __syncthreads();

    uint4* oh = (uint4*)(Ahi + (size_t)b*K0P);
    uint4* ol = (uint4*)(Alo + (size_t)b*K0P);
    const int inu = IN0 >> 3, main_u = NE*inu, NU = K0P >> 3;
    for (int u = tid; u < NU; u += 256){
        float v[8];
        if (u < main_u){
            int e = u/inu, i8 = (u - e*inu) << 3;
            float s = cf[e];
            #pragma unroll
            for (int l = 0; l < 8; l++) v[l] = x[i8+l]*s;
        } else {
            int j = (u - main_u) << 3;
            #pragma unroll
            for (int l = 0; l < 8; l++) v[l] = (j+l < NE) ? cf[j+l] : 0.0f;
        }
        uint4 hh, ll;
        split_pair(v[0],v[1],hh.x,ll.x); split_pair(v[2],v[3],hh.y,ll.y);
        split_pair(v[4],v[5],hh.z,ll.z); split_pair(v[6],v[7],hh.w,ll.w);
        oh[u] = hh; ol[u] = ll;
    }
}

// ---------------- A' build for layers 1/2: prev = elu(p0+p1) computed inline ----------------
__global__ __launch_bounds__(256) void prep_combine_kernel(
    const float* __restrict__ z,
    const float* __restrict__ p0, const float* __restrict__ p1,
    __nv_bfloat16* __restrict__ Ahi, __nv_bfloat16* __restrict__ Alo)
{
    constexpr int IN = INTER, KP = K1P;
    int b = blockIdx.x, tid = threadIdx.x;
    __shared__ float cf[NE];
    __shared__ float xp[HIDD];
    if (tid < NE) cf[tid] = g_coeff[b*NE + tid];
    // combine partials once into smem (512 floats)
    {
        const float4* a4 = (const float4*)(p0 + (size_t)b*NOUT);
        const float4* b4 = (const float4*)(p1 + (size_t)b*NOUT);
        float4* x4 = (float4*)xp;
        for (int i = tid; i < HIDD/4; i += 256){
            float4 u = a4[i], w = b4[i];
            float4 r;
            r.x = elu_f(u.x + w.x); r.y = elu_f(u.y + w.y);
            r.z = elu_f(u.z + w.z); r.w = elu_f(u.w + w.w);
            x4[i] = r;
        }
    }
    __syncthreads();

    const float4* z4 = (const float4*)(z + (size_t)b*LATD);
    uint4* oh = (uint4*)(Ahi + (size_t)b*KP);
    uint4* ol = (uint4*)(Alo + (size_t)b*KP);
    const int inu = IN >> 3, main_u = NE*inu, NU = KP >> 3;
    for (int u = tid; u < NU; u += 256){
        float v[8];
        if (u < main_u){
            int e = u/inu, i8 = (u - e*inu) << 3;
            float s = cf[e];
            if (i8 < LATD){
                float4 x0 = z4[i8>>2], x1 = z4[(i8>>2)+1];
                v[0]=x0.x*s; v[1]=x0.y*s; v[2]=x0.z*s; v[3]=x0.w*s;
                v[4]=x1.x*s; v[5]=x1.y*s; v[6]=x1.z*s; v[7]=x1.w*s;
            } else {
                int q = i8 - LATD;
                #pragma unroll
                for (int l = 0; l < 8; l++) v[l] = xp[q+l]*s;
            }
        } else {
            int j = (u - main_u) << 3;
            #pragma unroll
            for (int l = 0; l < 8; l++) v[l] = (j+l < NE) ? cf[j+l] : 0.0f;
        }
        uint4 hh, ll;
        split_pair(v[0],v[1],hh.x,ll.x); split_pair(v[2],v[3],hh.y,ll.y);
        split_pair(v[4],v[5],hh.z,ll.z); split_pair(v[6],v[7],hh.w,ll.w);
        oh[u] = hh; ol[u] = ll;
    }
}

// ---------------- final combine: out = p0 + p1 ----------------
__global__ __launch_bounds__(256) void combine_kernel(
    const float* __restrict__ p0, const float* __restrict__ p1, float* __restrict__ out)
{
    int i = blockIdx.x*256 + threadIdx.x;
    const float4* a4 = (const float4*)p0;
    const float4* b4 = (const float4*)p1;
    float4* o4 = (float4*)out;
    float4 u = a4[i], w = b4[i];
    float4 r; r.x = u.x+w.x; r.y = u.y+w.y; r.z = u.z+w.z; r.w = u.w+w.w;
    o4[i] = r;
}

// ---------------- mma.sync GEMM, split-K=2, 3-stage cp.async + reg double-buffer ----------------
#define STG_SZ 32768
#define GSMEM (3*STG_SZ)

template<int KP>
__global__ __launch_bounds__(256) void gemm_kernel(
    const __nv_bfloat16* __restrict__ Ahi, const __nv_bfloat16* __restrict__ Alo,
    const __nv_bfloat16* __restrict__ Whi, const __nv_bfloat16* __restrict__ Wlo,
    float* __restrict__ part0, float* __restrict__ part1, int split)
{
    constexpr int KTOT = KP/64;
    extern __shared__ char smem[];
    const uint32_t sb = smem_u32(smem);
    const int tid = threadIdx.x, wid = tid >> 5, L = tid & 31;
    const int m0 = blockIdx.y*64, n0 = blockIdx.x*64;
    const int wm = (wid & 1)*32, wn = (wid >> 1)*16;
    const int zz = blockIdx.z;
    const int t0 = zz ? split : 0;
    const int KT = zz ? (KTOT - split) : split;
    float* part = zz ? part1 : part0;

    uint32_t s_o[2];
    const __nv_bfloat16 *gah[2], *gal[2], *gbh[2], *gbl[2];
    #pragma unroll
    for (int r = 0; r < 2; r++){
        int ch = tid + r*256, row = ch >> 3, kc = ch & 7;
        s_o[r] = row*128 + ((kc*16) ^ ((row & 7) << 4));
        size_t kb0 = (size_t)t0*64 + kc*8;
        gah[r] = Ahi + (size_t)(m0+row)*KP + kb0;
        gal[r] = Alo + (size_t)(m0+row)*KP + kb0;
        gbh[r] = Whi + (size_t)(n0+row)*KP + kb0;
        gbl[r] = Wlo + (size_t)(n0+row)*KP + kb0;
    }

    const int alf = (L & 7) + ((L >> 3) & 1)*8;
    const int acb = (L >> 4)*16;
    const int axor = (alf & 7) << 4;
    const uint32_t arow0 = (uint32_t)(wm + alf)*128;
    const uint32_t arow1 = (uint32_t)(wm + 16 + alf)*128;
    const int blf = (L & 7) + (L >> 4)*8;
    const int bcb = ((L >> 3) & 1)*16;
    const int bxor = (blf & 7) << 4;
    const uint32_t brow = (uint32_t)(wn + blf)*128;

    float acc[2][2][4];
    #pragma unroll
    for (int i = 0; i < 2; i++)
        #pragma unroll
        for (int j = 0; j < 2; j++)
            #pragma unroll
            for (int q = 0; q < 4; q++) acc[i][j][q] = 0.0f;

    uint32_t fa[2][16], fb[2][8];

#define LOADFR(p, st, ks) do { \
    const uint32_t _ca = (uint32_t)(((ks)*32 + acb) ^ axor); \
    const uint32_t _cb = (uint32_t)(((ks)*32 + bcb) ^ bxor); \
    LDSM4(fa[p][0], fa[p][1], fa[p][2], fa[p][3],   (st) + arow0 + _ca); \
    LDSM4(fa[p][4], fa[p][5], fa[p][6], fa[p][7],   (st) + arow1 + _ca); \
    LDSM4(fa[p][8], fa[p][9], fa[p][10],fa[p][11],  (st) + 8192 + arow0 + _ca); \
    LDSM4(fa[p][12],fa[p][13],fa[p][14],fa[p][15],  (st) + 8192 + arow1 + _ca); \
    LDSM4(fb[p][0], fb[p][1], fb[p][2], fb[p][3],   (st) + 16384 + brow + _cb); \
    LDSM4(fb[p][4], fb[p][5], fb[p][6], fb[p][7],   (st) + 24576 + brow + _cb); \
} while(0)

#define DOMMA(p) do { \
    MMA16816(acc[0][0], fa[p][0], fa[p][1], fa[p][2], fa[p][3],  fb[p][0], fb[p][1]); \
    MMA16816(acc[0][1], fa[p][0], fa[p][1], fa[p][2], fa[p][3],  fb[p][2], fb[p][3]); \
    MMA16816(acc[1][0], fa[p][4], fa[p][5], fa[p][6], fa[p][7],  fb[p][0], fb[p][1]); \
    MMA16816(acc[1][1], fa[p][4], fa[p][5], fa[p][6], fa[p][7],  fb[p][2], fb[p][3]); \
    MMA16816(acc[0][0], fa[p][8], fa[p][9], fa[p][10],fa[p][11], fb[p][0], fb[p][1]); \
    MMA16816(acc[0][1], fa[p][8], fa[p][9], fa[p][10],fa[p][11], fb[p][2], fb[p][3]); \
    MMA16816(acc[1][0], fa[p][12],fa[p][13],fa[p][14],fa[p][15], fb[p][0], fb[p][1]); \
    MMA16816(acc[1][1], fa[p][12],fa[p][13],fa[p][14],fa[p][15], fb[p][2], fb[p][3]); \
    MMA16816(acc[0][0], fa[p][0], fa[p][1], fa[p][2], fa[p][3],  fb[p][4], fb[p][5]); \
    MMA16816(acc[0][1], fa[p][0], fa[p][1], fa[p][2], fa[p][3],  fb[p][6], fb[p][7]); \
    MMA16816(acc[1][0], fa[p][4], fa[p][5], fa[p][6], fa[p][7],  fb[p][4], fb[p][5]); \
    MMA16816(acc[1][1], fa[p][4], fa[p][5], fa[p][6], fa[p][7],  fb[p][6], fb[p][7]); \
} while(0)

    // prologue: tiles 0 and 1 of this split
    #pragma unroll
    for (int pt = 0; pt < 2; pt++){
        uint32_t st = sb + pt*STG_SZ;
        size_t kb = (size_t)pt*64;
        #pragma unroll
        for (int r = 0; r < 2; r++){
            CP16(st +         s_o[r], gah[r] + kb);
            CP16(st + 8192  + s_o[r], gal[r] + kb);
            CP16(st + 16384 + s_o[r], gbh[r] + kb);
            CP16(st + 24576 + s_o[r], gbl[r] + kb);
        }
        CP_COMMIT();
    }

    int stg = 0;
    for (int t = 0; t < KT; t++){
        if (t < KT-1) CP_WAIT1(); else CP_WAIT0();
        __syncthreads();

        if (t + 2 < KT){
            int ws = stg + 2; if (ws >= 3) ws -= 3;
            uint32_t st = sb + ws*STG_SZ;
            size_t kb = (size_t)(t+2)*64;
            #pragma unroll
            for (int r = 0; r < 2; r++){
                CP16(st +         s_o[r], gah[r] + kb);
                CP16(st + 8192  + s_o[r], gal[r] + kb);
                CP16(st + 16384 + s_o[r], gbh[r] + kb);
                CP16(st + 24576 + s_o[r], gbl[r] + kb);
            }
            CP_COMMIT();
        }

        const uint32_t st = sb + stg*STG_SZ;
        LOADFR(0, st, 0);
        LOADFR(1, st, 1);
        DOMMA(0);
        LOADFR(0, st, 2);
        DOMMA(1);
        LOADFR(1, st, 3);
        DOMMA(0);
        DOMMA(1);
        stg = (stg == 2) ? 0 : stg + 1;
    }

    const int g = L >> 2, tg = L & 3;
    #pragma unroll
    for (int i = 0; i < 2; i++){
        #pragma unroll
        for (int j = 0; j < 2; j++){
            int row = m0 + wm + i*16 + g;
            int col = n0 + wn + j*8 + 2*tg;
            float2 v0, v1;
            v0.x = acc[i][j][0]; v0.y = acc[i][j][1];
            v1.x = acc[i][j][2]; v1.y = acc[i][j][3];
            *(float2*)(part + (size_t)row*NOUT + col) = v0;
            *(float2*)(part + (size_t)(row+8)*NOUT + col) = v1;
        }
    }
#undef LOADFR
#undef DOMMA
}

extern "C" void kernel_launch(void* const* d_in, const int* in_sizes, int n_in,
                              void* d_out, int out_size)
{
    const float* z   = (const float*)d_in[0];
    const float* c   = (const float*)d_in[1];
    const float* w0  = (const float*)d_in[2];
    const float* b0  = (const float*)d_in[3];
    const float* w1  = (const float*)d_in[4];
    const float* b1  = (const float*)d_in[5];
    const float* w2  = (const float*)d_in[6];
    const float* b2  = (const float*)d_in[7];
    const float* gw1 = (const float*)d_in[8];
    const float* gb1 = (const float*)d_in[9];
    const float* gw2 = (const float*)d_in[10];
    const float* gb2 = (const float*)d_in[11];
    const float* gw3 = (const float*)d_in[12];
    const float* gb3 = (const float*)d_in[13];
    float* out = (float*)d_out;

    float *p0, *p1;
    __nv_bfloat16 *Ahi, *Alo, *W0hi, *W0lo, *W1hi, *W1lo, *W2hi, *W2lo;
    cudaGetSymbolAddress((void**)&p0, g_part0);
    cudaGetSymbolAddress((void**)&p1, g_part1);
    cudaGetSymbolAddress((void**)&Ahi, g_Ahi);
    cudaGetSymbolAddress((void**)&Alo, g_Alo);
    cudaGetSymbolAddress((void**)&W0hi, g_W0hi);
    cudaGetSymbolAddress((void**)&W0lo, g_W0lo);
    cudaGetSymbolAddress((void**)&W1hi, g_W1hi);
    cudaGetSymbolAddress((void**)&W1lo, g_W1lo);
    cudaGetSymbolAddress((void**)&W2hi, g_W2hi);
    cudaGetSymbolAddress((void**)&W2lo, g_W2lo);

    cudaFuncSetAttribute(gemm_kernel<K0P>, cudaFuncAttributeMaxDynamicSharedMemorySize, GSMEM);
    cudaFuncSetAttribute(gemm_kernel<K1P>, cudaFuncAttributeMaxDynamicSharedMemorySize, GSMEM);

    dim3 gg(8, 16, 2);   // 256 CTAs, split-K=2

    transpose_all<<<dim3(K1P/32, 16, 3), dim3(32, 8)>>>(w0, b0, w1, b1, w2, b2);
    gate_prep_kernel<<<B_SZ, 256>>>(z, c, gw1, gb1, gw2, gb2, gw3, gb3, Ahi, Alo);
    gemm_kernel<K0P><<<gg, 256, GSMEM>>>(Ahi, Alo, W0hi, W0lo, p0, p1, 21);

    prep_combine_kernel<<<B_SZ, 256>>>(z, p0, p1, Ahi, Alo);
    gemm_kernel<K1P><<<gg, 256, GSMEM>>>(Ahi, Alo, W1hi, W1lo, p0, p1, 37);

    prep_combine_kernel<<<B_SZ, 256>>>(z, p0, p1, Ahi, Alo);
    gemm_kernel<K1P><<<gg, 256, GSMEM>>>(Ahi, Alo, W2hi, W2lo, p0, p1, 37);

    combine_kernel<<<B_SZ*NOUT/1024, 256>>>(p0, p1, out);
}